// round 8
// baseline (speedup 1.0000x reference)
#include <cuda_runtime.h>

// Conv2d 3x3, stride 1, pad 1, NCHW fp32 — f32x2 FFMA, cp.async double-buffered,
// ICB=16 (4 chunks), 1 barrier/chunk, partial unroll for I$.
// x: [32, 64, 112, 112], w: [128, 64, 3, 3], b: [128] -> out: [32, 128, 112, 112]

#define CN 32
#define CC 64
#define CH 112
#define CW 112
#define CK 128

#define OC_TILE 32
#define H_TILE  16
#define W_TILE  28
#define ICB     16
#define PW       7
#define IN_H    (H_TILE + 2)   // 18
#define IN_W    (W_TILE + 2)   // 30
#define IN_STRIDE 31           // >= IN_W, odd stride breaks most bank conflicts

#define IN_BUF   (ICB * IN_H * IN_STRIDE)   // 8928 floats
#define W_BUF    (ICB * 9 * OC_TILE)        // 4608 floats
#define SMEM_FLOATS (2 * IN_BUF + 2 * W_BUF)
#define SMEM_BYTES  (SMEM_FLOATS * 4)       // 108,288 B -> 2 CTAs/SM

typedef unsigned long long u64;

__device__ __forceinline__ u64 dup_f32x2(float v) {
    u64 d;
    asm("mov.b64 %0, {%1, %1};" : "=l"(d) : "f"(v));
    return d;
}

__device__ __forceinline__ u64 pack_f32x2(float lo, float hi) {
    u64 d;
    asm("mov.b64 %0, {%1, %2};" : "=l"(d) : "f"(lo), "f"(hi));
    return d;
}

__device__ __forceinline__ u64 ffma2(u64 a, u64 b, u64 c) {
    u64 d;
    asm("fma.rn.f32x2 %0, %1, %2, %3;" : "=l"(d) : "l"(a), "l"(b), "l"(c));
    return d;
}

__device__ __forceinline__ void cp_async4(unsigned dst, const void* src, bool ok) {
    int sz = ok ? 4 : 0;   // src-size 0 -> zero-fill destination
    asm volatile("cp.async.ca.shared.global [%0], [%1], 4, %2;"
                 :: "r"(dst), "l"(src), "r"(sz));
}

__device__ __forceinline__ void cp_commit() {
    asm volatile("cp.async.commit_group;");
}

__device__ __forceinline__ void cp_wait_all() {
    asm volatile("cp.async.wait_group 0;");
}

__global__ __launch_bounds__(256, 2)
void conv3x3_kernel(const float* __restrict__ x,
                    const float* __restrict__ wgt,
                    const float* __restrict__ bias,
                    float* __restrict__ out) {
    extern __shared__ float smem[];
    float* s_in_base = smem;                 // [2][IN_BUF]
    float* s_w_base  = smem + 2 * IN_BUF;    // [2][W_BUF]

    const int tid  = threadIdx.x;
    const int wseg = tid & 3;
    const int row  = (tid >> 2) & 15;
    const int ocg  = tid >> 6;

    const int sp = blockIdx.x;
    const int hb = sp >> 2;
    const int wb = sp & 3;
    const int ocb = blockIdx.y * OC_TILE;
    const int n   = blockIdx.z;

    const int h0 = hb * H_TILE - 1;
    const int w0 = wb * W_TILE - 1;

    const float* xn = x + (size_t)n * CC * CH * CW;

    // staging: 8 lane-groups of 32, group = ic (two passes for ICB=16); lane = column
    const int st_ic = tid >> 5;            // 0..7
    const int st_c  = tid & 31;            // 0..31 (>=30 idle)
    const int st_gw = w0 + st_c;
    const bool st_wok = (st_c < IN_W) && ((unsigned)st_gw < CW);

    auto stage = [&](int icb, int buf) {
        float* si = s_in_base + buf * IN_BUF;
        float* sw = s_w_base  + buf * W_BUF;
        if (st_c < IN_W) {
#pragma unroll
            for (int j = 0; j < 2; j++) {
                int ic = st_ic + 8 * j;
                const float* src_base = xn + (size_t)(icb + ic) * CH * CW + st_gw;
                unsigned dst = (unsigned)__cvta_generic_to_shared(
                    si + (ic * IN_H) * IN_STRIDE + st_c);
#pragma unroll
                for (int r = 0; r < IN_H; r++) {
                    int gh = h0 + r;
                    bool ok = st_wok && ((unsigned)gh < CH);
                    const float* src = ok ? (src_base + gh * CW) : xn;
                    cp_async4(dst, src, ok);
                    dst += IN_STRIDE * 4;
                }
            }
        }
#pragma unroll
        for (int j = 0; j < 18; j++) {
            int idx = j * 256 + tid;       // 0..4607
            int oc = idx & 31;
            int t  = idx >> 5;             // 0..143
            int ic = t / 9;
            int k  = t - ic * 9;
            cp_async4((unsigned)__cvta_generic_to_shared(sw + idx),
                      wgt + ((size_t)(ocb + oc) * CC + (icb + ic)) * 9 + k, true);
        }
        cp_commit();
    };

    // accumulators: 4 oc-pairs x 7 pixels, init with packed bias {b_even, b_odd}
    u64 acc[4][PW];
#pragma unroll
    for (int q = 0; q < 4; q++) {
        int oc0 = ocb + ocg * 8 + 2 * q;
        u64 b2 = pack_f32x2(bias[oc0], bias[oc0 + 1]);
#pragma unroll
        for (int p = 0; p < PW; p++) acc[q][p] = b2;
    }

    stage(0, 0);

    int buf = 0;
    for (int cidx = 0; cidx < CC / ICB; cidx++) {
        cp_wait_all();
        __syncthreads();   // chunk `cidx` visible; also orders prior chunk's readers
                           // before the re-stage below (no second barrier needed)

        if (cidx + 1 < CC / ICB)
            stage((cidx + 1) * ICB, buf ^ 1);

        const float* si = s_in_base + buf * IN_BUF;
        const float* sw = s_w_base  + buf * W_BUF;

#pragma unroll 4                           // cap unroll: keep SASS body inside L1.5 I$
        for (int ic = 0; ic < ICB; ic++) {
#pragma unroll
            for (int kh = 0; kh < 3; kh++) {
                const float* ip = si + (ic * IN_H + row + kh) * IN_STRIDE + wseg * PW;
                u64 in2[PW + 2];
#pragma unroll
                for (int p = 0; p < PW + 2; p++) in2[p] = dup_f32x2(ip[p]);

                const float* wp = sw + (ic * 9 + kh * 3) * OC_TILE + ocg * 8;
#pragma unroll
                for (int kw = 0; kw < 3; kw++) {
                    ulonglong2 wa = *(const ulonglong2*)(wp + kw * OC_TILE);
                    ulonglong2 wb2 = *(const ulonglong2*)(wp + kw * OC_TILE + 4);
                    u64 w2[4] = {wa.x, wa.y, wb2.x, wb2.y};
#pragma unroll
                    for (int q = 0; q < 4; q++)
#pragma unroll
                        for (int p = 0; p < PW; p++)
                            acc[q][p] = ffma2(in2[p + kw], w2[q], acc[q][p]);
                }
            }
        }
        buf ^= 1;
    }

    // ---- epilogue: unpack + store (bias already folded in) ----
    const int oh  = hb * H_TILE + row;
    const int ow0 = wb * W_TILE + wseg * PW;
#pragma unroll
    for (int q = 0; q < 4; q++) {
        int oc0 = ocb + ocg * 8 + 2 * q;
        float* op0 = out + (((size_t)n * CK + oc0) * CH + oh) * CW + ow0;
        float* op1 = op0 + (size_t)CH * CW;
#pragma unroll
        for (int p = 0; p < PW; p++) {
            float lo, hi;
            asm("mov.b64 {%0, %1}, %2;" : "=f"(lo), "=f"(hi) : "l"(acc[q][p]));
            op0[p] = lo;
            op1[p] = hi;
        }
    }
}

extern "C" void kernel_launch(void* const* d_in, const int* in_sizes, int n_in,
                              void* d_out, int out_size) {
    const float* x    = (const float*)d_in[0];
    const float* wgt  = (const float*)d_in[1];
    const float* bias = (const float*)d_in[2];
    float* out        = (float*)d_out;

    cudaFuncSetAttribute(conv3x3_kernel,
                         cudaFuncAttributeMaxDynamicSharedMemorySize, SMEM_BYTES);

    dim3 grid(28, CK / OC_TILE, CN);
    conv3x3_kernel<<<grid, 256, SMEM_BYTES>>>(x, wgt, bias, out);
}

// round 11
// speedup vs baseline: 1.9643x; 1.9643x over previous
#include <cuda_runtime.h>
#include <cuda_bf16.h>
#include <cstdint>

// Conv2d 3x3 s1 p1 NCHW fp32 via implicit GEMM on mma.sync.m16n8k16 (bf16 3-split).
// x:[32,64,112,112] w:[128,64,3,3] b:[128] -> out:[32,128,112,112]
// Per CTA: D[128 pix,128 oc] = Patch[128,576] . W[128,576]^T, K-chunks of 16.

#define CHh 112
#define CWw 112
#define CCI 64
#define CKo 128
#define KTOT 576
#define TH 8
#define TW 16
#define RAW_RS 18          // (TW+2) floats
#define RAW_ICS 180        // (TH+2)*RAW_RS
#define RAW_TOT 11520      // 64*180 floats
#define KC 16
#define NCHUNK 36
#define TSTRIDE_B 48       // bf16 tile row stride bytes (16 k * 2B + 16 pad); odd*16B
#define TILE_B (128 * TSTRIDE_B)   // 6144 B per split tile

// smem byte offsets
#define OFF_KOFF 0                  // int[576]  = 2304 B
#define OFF_RAW  2304               // fp32 raw tile, 46080 B
#define OFF_A    48384              // [2 buf][2 split] * 6144 = 24576
#define OFF_B    72960              // same, 24576
#define SMEM_BYTES 97536
#define OFF_EPI  2304               // epilogue f32 [128 oc][132 pix] = 67584 (reuses RAW/A)

__device__ __forceinline__ uint32_t smem_u32(const void* p) {
    uint32_t a;
    asm("{ .reg .u64 t; cvta.to.shared.u64 t, %1; cvt.u32.u64 %0, t; }"
        : "=r"(a) : "l"(p));
    return a;
}

__device__ __forceinline__ void cp_async4(uint32_t dst, const void* src, bool ok) {
    int sz = ok ? 4 : 0;
    asm volatile("cp.async.ca.shared.global [%0], [%1], 4, %2;"
                 :: "r"(dst), "l"(src), "r"(sz));
}

// split float pair -> packed bf16x2 hi + packed bf16x2 lo-residual (lane0 = v0)
__device__ __forceinline__ void split2(float v0, float v1, uint32_t& hp, uint32_t& lp) {
    asm("cvt.rn.bf16x2.f32 %0, %1, %2;" : "=r"(hp) : "f"(v1), "f"(v0));
    float h0 = __uint_as_float(hp << 16);
    float h1 = __uint_as_float(hp & 0xFFFF0000u);
    float l0 = v0 - h0, l1 = v1 - h1;
    asm("cvt.rn.bf16x2.f32 %0, %1, %2;" : "=r"(lp) : "f"(l1), "f"(l0));
}

#define LDSM4(r, addr) \
    asm volatile("ldmatrix.sync.aligned.m8n8.x4.shared.b16 {%0,%1,%2,%3}, [%4];" \
                 : "=r"((r)[0]), "=r"((r)[1]), "=r"((r)[2]), "=r"((r)[3]) : "r"(addr))

#define MMA16816(d, a, b0v, b1v) \
    asm volatile("mma.sync.aligned.m16n8k16.row.col.f32.bf16.bf16.f32 " \
                 "{%0,%1,%2,%3}, {%4,%5,%6,%7}, {%8,%9}, {%0,%1,%2,%3};" \
                 : "+f"((d)[0]), "+f"((d)[1]), "+f"((d)[2]), "+f"((d)[3]) \
                 : "r"((a)[0]), "r"((a)[1]), "r"((a)[2]), "r"((a)[3]), \
                   "r"(b0v), "r"(b1v))

__global__ __launch_bounds__(256, 2)
void conv3x3_mma_kernel(const float* __restrict__ x,
                        const float* __restrict__ wgt,
                        const float* __restrict__ bias,
                        float* __restrict__ out) {
    extern __shared__ char smem[];
    const uint32_t sbase = smem_u32(smem);
    const int tid  = threadIdx.x;
    const int lane = tid & 31;
    const int wid  = tid >> 5;
    const int warp_m = wid & 3;          // 4 warps along M (pixels)
    const int warp_n = wid >> 2;         // 2 warps along N (ocs)

    const int ow0 = blockIdx.x * TW;
    const int oh0 = blockIdx.y * TH;
    const int n   = blockIdx.z;

    // ---- tap-offset LUT ----
    int* koff = (int*)(smem + OFF_KOFF);
    for (int k = tid; k < KTOT; k += 256) {
        int ic = k / 9, t = k - ic * 9, kh = t / 3, kw = t - kh * 3;
        koff[k] = ic * RAW_ICS + kh * RAW_RS + kw;
    }

    // ---- raw input tile via cp.async (zero-padded halo) ----
    const float* xn = x + (size_t)n * CCI * CHh * CWw;
    {
        const int h0 = oh0 - 1, w0 = ow0 - 1;
#pragma unroll 5
        for (int j = 0; j < RAW_TOT / 256; j++) {
            int idx = j * 256 + tid;
            int ic  = idx / RAW_ICS;
            int rem = idx - ic * RAW_ICS;
            int rr  = rem / RAW_RS;
            int c2  = rem - rr * RAW_RS;
            int gh = h0 + rr, gw = w0 + c2;
            bool ok = ((unsigned)gh < CHh) && ((unsigned)gw < CWw);
            const float* src = ok ? (xn + (size_t)ic * CHh * CWw + gh * CWw + gw) : xn;
            cp_async4(sbase + OFF_RAW + idx * 4, src, ok);
        }
        asm volatile("cp.async.commit_group;");
        asm volatile("cp.async.wait_group 0;");
    }
    __syncthreads();

    const float* sraw = (const float*)(smem + OFF_RAW);

    // ---- per-chunk staging: warps 0-3 build A (im2col), warps 4-7 build B ----
    const int st_pix = tid & 127;                   // A: pixel; B: oc
    const int st_prc = (st_pix >> 4) * RAW_RS + (st_pix & 15);

    auto stage = [&](int cc, int buf) {
        const int kbase = cc * KC;
        if (tid < 128) {                            // A: one pixel, 16 k taps
            float v[KC];
#pragma unroll
            for (int kk = 0; kk < KC; kk++)
                v[kk] = sraw[koff[kbase + kk] + st_prc];
            uint32_t hp[8], lp[8];
#pragma unroll
            for (int i = 0; i < 8; i++) split2(v[2 * i], v[2 * i + 1], hp[i], lp[i]);
            uint32_t ah = sbase + OFF_A + (buf * 2 + 0) * TILE_B + st_pix * TSTRIDE_B;
            uint32_t al = sbase + OFF_A + (buf * 2 + 1) * TILE_B + st_pix * TSTRIDE_B;
            asm volatile("st.shared.v4.b32 [%0], {%1,%2,%3,%4};" :: "r"(ah),
                         "r"(hp[0]), "r"(hp[1]), "r"(hp[2]), "r"(hp[3]));
            asm volatile("st.shared.v4.b32 [%0], {%1,%2,%3,%4};" :: "r"(ah + 16),
                         "r"(hp[4]), "r"(hp[5]), "r"(hp[6]), "r"(hp[7]));
            asm volatile("st.shared.v4.b32 [%0], {%1,%2,%3,%4};" :: "r"(al),
                         "r"(lp[0]), "r"(lp[1]), "r"(lp[2]), "r"(lp[3]));
            asm volatile("st.shared.v4.b32 [%0], {%1,%2,%3,%4};" :: "r"(al + 16),
                         "r"(lp[4]), "r"(lp[5]), "r"(lp[6]), "r"(lp[7]));
        } else {                                    // B: one oc, 16 k
            const float* wp = wgt + (size_t)st_pix * KTOT + kbase;
            float4 w0 = *(const float4*)(wp);
            float4 w1 = *(const float4*)(wp + 4);
            float4 w2 = *(const float4*)(wp + 8);
            float4 w3 = *(const float4*)(wp + 12);
            float v[KC] = {w0.x, w0.y, w0.z, w0.w, w1.x, w1.y, w1.z, w1.w,
                           w2.x, w2.y, w2.z, w2.w, w3.x, w3.y, w3.z, w3.w};
            uint32_t hp[8], lp[8];
#pragma unroll
            for (int i = 0; i < 8; i++) split2(v[2 * i], v[2 * i + 1], hp[i], lp[i]);
            uint32_t bh = sbase + OFF_B + (buf * 2 + 0) * TILE_B + st_pix * TSTRIDE_B;
            uint32_t bl = sbase + OFF_B + (buf * 2 + 1) * TILE_B + st_pix * TSTRIDE_B;
            asm volatile("st.shared.v4.b32 [%0], {%1,%2,%3,%4};" :: "r"(bh),
                         "r"(hp[0]), "r"(hp[1]), "r"(hp[2]), "r"(hp[3]));
            asm volatile("st.shared.v4.b32 [%0], {%1,%2,%3,%4};" :: "r"(bh + 16),
                         "r"(hp[4]), "r"(hp[5]), "r"(hp[6]), "r"(hp[7]));
            asm volatile("st.shared.v4.b32 [%0], {%1,%2,%3,%4};" :: "r"(bl),
                         "r"(lp[0]), "r"(lp[1]), "r"(lp[2]), "r"(lp[3]));
            asm volatile("st.shared.v4.b32 [%0], {%1,%2,%3,%4};" :: "r"(bl + 16),
                         "r"(lp[4]), "r"(lp[5]), "r"(lp[6]), "r"(lp[7]));
        }
    };

    // ldmatrix per-lane row offsets (48B stride: conflict-free, r*3 mod 8 is a perm)
    uint32_t a_off[2], b_off[4];
#pragma unroll
    for (int mi = 0; mi < 2; mi++)
        a_off[mi] = (uint32_t)((warp_m * 32 + mi * 16 + (lane & 15)) * TSTRIDE_B
                               + ((lane >> 4) << 4));
#pragma unroll
    for (int nt = 0; nt < 4; nt++)
        b_off[nt] = (uint32_t)((warp_n * 64 + nt * 16 + (lane & 15)) * TSTRIDE_B
                               + ((lane >> 4) << 4));

    float acc[2][8][4];
#pragma unroll
    for (int mi = 0; mi < 2; mi++)
#pragma unroll
        for (int ni = 0; ni < 8; ni++)
#pragma unroll
            for (int e = 0; e < 4; e++) acc[mi][ni][e] = 0.0f;

    stage(0, 0);
    __syncthreads();

    for (int cc = 0; cc < NCHUNK; cc++) {
        const int buf = cc & 1;
        if (cc + 1 < NCHUNK) stage(cc + 1, buf ^ 1);   // overlap with mma below

        uint32_t afr[2][2][4];                         // [split][mi]
#pragma unroll
        for (int s = 0; s < 2; s++)
#pragma unroll
            for (int mi = 0; mi < 2; mi++)
                LDSM4(afr[s][mi], sbase + OFF_A + (buf * 2 + s) * TILE_B + a_off[mi]);

#pragma unroll
        for (int nt = 0; nt < 4; nt++) {
            uint32_t bhf[4], blf[4];
            LDSM4(bhf, sbase + OFF_B + (buf * 2 + 0) * TILE_B + b_off[nt]);
            LDSM4(blf, sbase + OFF_B + (buf * 2 + 1) * TILE_B + b_off[nt]);
#pragma unroll
            for (int h = 0; h < 2; h++) {
                uint32_t bh0 = bhf[h], bh1 = bhf[h + 2];
                uint32_t bl0 = blf[h], bl1 = blf[h + 2];
#pragma unroll
                for (int mi = 0; mi < 2; mi++) {
                    float* d = acc[mi][nt * 2 + h];
                    MMA16816(d, afr[0][mi], bh0, bh1);   // Ahi . Bhi
                    MMA16816(d, afr[0][mi], bl0, bl1);   // Ahi . Blo
                    MMA16816(d, afr[1][mi], bh0, bh1);   // Alo . Bhi
                }
            }
        }
        __syncthreads();
    }

    // ---- epilogue: transpose through smem, then coalesced stores with bias ----
    float* se = (float*)(smem + OFF_EPI);          // [128 oc][132]
#pragma unroll
    for (int mi = 0; mi < 2; mi++)
#pragma unroll
        for (int ni = 0; ni < 8; ni++) {
            int p0 = warp_m * 32 + mi * 16 + (lane >> 2);
            int q0 = warp_n * 64 + ni * 8 + (lane & 3) * 2;
            se[q0 * 132 + p0]           = acc[mi][ni][0];
            se[(q0 + 1) * 132 + p0]     = acc[mi][ni][1];
            se[q0 * 132 + p0 + 8]       = acc[mi][ni][2];
            se[(q0 + 1) * 132 + p0 + 8] = acc[mi][ni][3];
        }
    __syncthreads();

#pragma unroll
    for (int it = 0; it < 16; it++) {
        int i  = it * 256 + tid;         // float4 id, 4096 total
        int oc = i >> 5;
        int rem = i & 31;
        int rr = rem >> 2, c4 = rem & 3;
        float4 v = *(const float4*)(se + oc * 132 + rr * 16 + c4 * 4);
        float b = bias[oc];
        v.x += b; v.y += b; v.z += b; v.w += b;
        *(float4*)(out + (((size_t)n * CKo + oc) * CHh + oh0 + rr) * CWw + ow0 + c4 * 4) = v;
    }
}

extern "C" void kernel_launch(void* const* d_in, const int* in_sizes, int n_in,
                              void* d_out, int out_size) {
    const float* x    = (const float*)d_in[0];
    const float* wgt  = (const float*)d_in[1];
    const float* bias = (const float*)d_in[2];
    float* out        = (float*)d_out;

    cudaFuncSetAttribute(conv3x3_mma_kernel,
                         cudaFuncAttributeMaxDynamicSharedMemorySize, SMEM_BYTES);

    dim3 grid(CWw / TW /*7*/, CHh / TH /*14*/, 32);
    conv3x3_mma_kernel<<<grid, 256, SMEM_BYTES>>>(x, wgt, bias, out);
}